// round 14
// baseline (speedup 1.0000x reference)
#include <cuda_runtime.h>
#include <cuda_bf16.h>
#include <cuda_fp16.h>

#define D 128
#define NREL_HALF 24
#define BN_EPS 1e-5f
#define MAX_NODES 100000
#define MAX_EDGES 1600000
#define GATHER_GRID 592   // 4 blocks/SM x 148 SMs: co-residency guaranteed
#define CSR_GRID 592
#define CSR_CHUNK 169     // ceil(100000 / 592); 592*169 = 100048

// Scratch: device globals (no allocations allowed).
__device__ __half g_fh[MAX_NODES * 128];     // 25.6 MB: x @ W in fp16
__device__ int    g_cnt[MAX_NODES];          // per-dst degree
__device__ int    g_off[MAX_NODES + 1];      // CSR offsets
__device__ int    g_cursor[MAX_NODES];       // reorder cursors
__device__ int2   g_epack[MAX_EDGES];        // CSR: {src, alpha_bits} per slot
__device__ int    g_bsums[640];              // per-block scan sums (592 used)
__device__ float  g_stats[256];              // col sums / col sumsq
__device__ int    g_bar;                     // gather grid-barrier counter
__device__ int    g_cbar;                    // csr grid-barrier counter

// Host-side stream/events for fork-join overlap (created once; host resources
// only — no device memory). Graph capture records these as parallel branches.
static cudaStream_t g_s2;
static cudaEvent_t  g_evFork, g_evJoin;
static struct _StreamInit {
    _StreamInit() {
        cudaStreamCreateWithFlags(&g_s2, cudaStreamNonBlocking);
        cudaEventCreateWithFlags(&g_evFork, cudaEventDisableTiming);
        cudaEventCreateWithFlags(&g_evJoin, cudaEventDisableTiming);
    }
} g_streamInit;

// ---------------------------------------------------------------------------
// feats = x @ W on tensor cores: 3-term bf16 split (hi*hi + hi*lo + lo*hi),
// fp32 accumulate, fp16 output.
// ---------------------------------------------------------------------------
__device__ __forceinline__ void cvt_split2(float2 v, unsigned& hi, unsigned& lo) {
    __nv_bfloat16 h0 = __float2bfloat16(v.x);
    __nv_bfloat16 h1 = __float2bfloat16(v.y);
    __nv_bfloat16 l0 = __float2bfloat16(v.x - __bfloat162float(h0));
    __nv_bfloat16 l1 = __float2bfloat16(v.y - __bfloat162float(h1));
    hi = (unsigned)__bfloat16_as_ushort(h0) |
         ((unsigned)__bfloat16_as_ushort(h1) << 16);
    lo = (unsigned)__bfloat16_as_ushort(l0) |
         ((unsigned)__bfloat16_as_ushort(l1) << 16);
}

#define MMA_BF16(d, a, b)                                                   \
    asm volatile(                                                           \
        "mma.sync.aligned.m16n8k16.row.col.f32.bf16.bf16.f32 "              \
        "{%0,%1,%2,%3}, {%4,%5,%6,%7}, {%8,%9}, {%0,%1,%2,%3};"             \
        : "+f"(d[0]), "+f"(d[1]), "+f"(d[2]), "+f"(d[3])                    \
        : "r"(a[0]), "r"(a[1]), "r"(a[2]), "r"(a[3]), "r"(b.x), "r"(b.y))

__global__ void gemm_kernel(const float* __restrict__ x,
                            const float* __restrict__ w,
                            int n_rows) {
    // [split][n-tile t][k-tile u][lane] -> uint2 {b0, b1}; 32 KB total.
    __shared__ uint2 sW[2][8][8][32];

    const int tid  = threadIdx.x;
    const int ch   = blockIdx.y;           // 64-col half
    const int lane = tid & 31;
    const int wid  = tid >> 5;

    // Stage + split W[k][ch*64+n] into fragment layout (8192 elements).
    for (int idx = tid; idx < 8192; idx += 256) {
        int k = idx >> 6, n = idx & 63;
        float v = __ldg(w + k * 128 + ch * 64 + n);
        __nv_bfloat16 h = __float2bfloat16(v);
        __nv_bfloat16 l = __float2bfloat16(v - __bfloat162float(h));
        int t = n >> 3, nin = n & 7;
        int u = k >> 4, kin = k & 15;
        int reg = (kin >> 3) & 1;          // b0 (k 0-7) or b1 (k 8-15)
        int half = kin & 1;
        int ln = nin * 4 + ((kin & 7) >> 1);
        unsigned short* ph = (unsigned short*)&sW[0][t][u][ln];
        unsigned short* pl = (unsigned short*)&sW[1][t][u][ln];
        ph[reg * 2 + half] = __bfloat16_as_ushort(h);
        pl[reg * 2 + half] = __bfloat16_as_ushort(l);
    }
    __syncthreads();

    const int r0   = blockIdx.x * 128 + wid * 16;
    const int rA   = r0 + (lane >> 2);          // rows lane/4 and +8
    const int rB   = rA + 8;
    const int rAc  = min(rA, n_rows - 1);       // clamped for loads
    const int rBc  = min(rB, n_rows - 1);
    const int kcol = (lane & 3) * 2;

    const float* xA = x + (size_t)rAc * 128;
    const float* xB = x + (size_t)rBc * 128;

    float acc[8][4];
#pragma unroll
    for (int t = 0; t < 8; t++)
#pragma unroll
        for (int j = 0; j < 4; j++) acc[t][j] = 0.f;

#pragma unroll
    for (int u = 0; u < 8; u++) {
        int k0 = u * 16 + kcol;
        float2 vA0 = *(const float2*)(xA + k0);
        float2 vA1 = *(const float2*)(xA + k0 + 8);
        float2 vB0 = *(const float2*)(xB + k0);
        float2 vB1 = *(const float2*)(xB + k0 + 8);
        unsigned ahi[4], alo[4];
        cvt_split2(vA0, ahi[0], alo[0]);
        cvt_split2(vB0, ahi[1], alo[1]);
        cvt_split2(vA1, ahi[2], alo[2]);
        cvt_split2(vB1, ahi[3], alo[3]);
#pragma unroll
        for (int t = 0; t < 8; t++) {
            uint2 bh = sW[0][t][u][lane];
            uint2 bl = sW[1][t][u][lane];
            MMA_BF16(acc[t], ahi, bh);
            MMA_BF16(acc[t], ahi, bl);
            MMA_BF16(acc[t], alo, bh);
        }
    }

    // Epilogue: fp16 half2 stores, guarded for the ragged last block.
    const int cbase = ch * 64 + kcol;  // (lane&3)*2 within each n-tile
    if (rA < n_rows) {
        __half* po = g_fh + (size_t)rA * 128 + cbase;
#pragma unroll
        for (int t = 0; t < 8; t++)
            *(__half2*)(po + t * 8) = __floats2half2_rn(acc[t][0], acc[t][1]);
    }
    if (rB < n_rows) {
        __half* po = g_fh + (size_t)rB * 128 + cbase;
#pragma unroll
        for (int t = 0; t < 8; t++)
            *(__half2*)(po + t * 8) = __floats2half2_rn(acc[t][2], acc[t][3]);
    }
}

// ---------------------------------------------------------------------------
// CSR grid barrier: monotonic targets; g_cbar reset by gather_kernel (which
// runs strictly after this kernel every launch).
// ---------------------------------------------------------------------------
__device__ __forceinline__ void grid_bar_csr(int target) {
    __threadfence();
    __syncthreads();
    if (threadIdx.x == 0) {
        atomicAdd(&g_cbar, 1);
        while (*(volatile int*)&g_cbar < target) { }
    }
    __syncthreads();
    __threadfence();
}

// ---------------------------------------------------------------------------
// Fused persistent CSR build: zero -> hist -> block scan -> prefix+cursors
// -> reorder, all in one kernel with grid barriers.
// Grid MUST be CSR_GRID with __launch_bounds__(256,4): co-residency (4 x 148)
// guarantees barrier progress (and concurrent GEMM terminates independently,
// so delayed placement can never deadlock).
// ---------------------------------------------------------------------------
__global__ void __launch_bounds__(256, 4)
csr_kernel(const int4* __restrict__ src4,
           const int4* __restrict__ dst4,
           const int4* __restrict__ et4,
           const float* __restrict__ alpha,
           int n_nodes, int n_edges) {
    const int t    = threadIdx.x;
    const int gtid = blockIdx.x * 256 + t;
    const int nthr = gridDim.x * 256;
    const int n_edges4 = n_edges >> 2;

    // P0: zero degree counters + gather stats + gather barrier.
    for (int i = gtid; i < n_nodes; i += nthr) g_cnt[i] = 0;
    if (gtid < 256) g_stats[gtid] = 0.f;
    if (gtid == 0) g_bar = 0;
    grid_bar_csr(1 * CSR_GRID);

    // P1: histogram of destinations (int4, 4 edges/thread/iter).
    for (int i = gtid; i < n_edges4; i += nthr) {
        int4 d = __ldg(dst4 + i);
        atomicAdd(&g_cnt[d.x], 1);
        atomicAdd(&g_cnt[d.y], 1);
        atomicAdd(&g_cnt[d.z], 1);
        atomicAdd(&g_cnt[d.w], 1);
    }
    grid_bar_csr(2 * CSR_GRID);

    // P2: per-block exclusive scan of this block's CSR_CHUNK counts.
    __shared__ int wsum[8];
    const int base = blockIdx.x * CSR_CHUNK;
    int len = n_nodes - base;
    if (len > CSR_CHUNK) len = CSR_CHUNK;   // always > 0 for n=100000

    int v = (t < len) ? g_cnt[base + t] : 0;
    const int lane = t & 31, wrp = t >> 5;
    int inc = v;
#pragma unroll
    for (int o = 1; o < 32; o <<= 1) {
        int y = __shfl_up_sync(0xffffffffu, inc, o);
        if (lane >= o) inc += y;
    }
    if (lane == 31) wsum[wrp] = inc;
    __syncthreads();
    if (t == 0) {
        int s = 0;
#pragma unroll
        for (int i = 0; i < 8; i++) { int c = wsum[i]; wsum[i] = s; s += c; }
        g_bsums[blockIdx.x] = s;
    }
    __syncthreads();
    int excl = inc - v + wsum[wrp];
    if (t < len) g_off[base + t] = excl;
    grid_bar_csr(3 * CSR_GRID);

    // P3: add prefix of earlier blocks' sums; init cursors.
    __shared__ int red[256];
    int part = 0;
    for (int j = t; j < blockIdx.x; j += 256) part += g_bsums[j];
    red[t] = part;
    __syncthreads();
#pragma unroll
    for (int s2 = 128; s2 > 0; s2 >>= 1) {
        if (t < s2) red[t] += red[t + s2];
        __syncthreads();
    }
    int prefix = red[0];
    if (t < len) {
        int o = g_off[base + t] + prefix;
        g_off[base + t] = o;
        g_cursor[base + t] = o;
    }
    if (blockIdx.x == gridDim.x - 1 && t == 0) g_off[n_nodes] = n_edges;
    grid_bar_csr(4 * CSR_GRID);

    // P4: reorder edges into CSR slots; premultiply alpha.
    for (int i = gtid; i < n_edges4; i += nthr) {
        int4 s = __ldg(src4 + i);
        int4 d = __ldg(dst4 + i);
        int4 ty = __ldg(et4 + i);
        const int ss[4] = {s.x, s.y, s.z, s.w};
        const int dd[4] = {d.x, d.y, d.z, d.w};
        const int tt[4] = {ty.x, ty.y, ty.z, ty.w};
#pragma unroll
        for (int j = 0; j < 4; j++) {
            int y = tt[j];
            int tr = (y >= NREL_HALF) ? y - NREL_HALF : y + NREL_HALF;
            float alp = __ldg(alpha + y) + __ldg(alpha + tr);
            int pos = atomicAdd(&g_cursor[dd[j]], 1);
            g_epack[pos] = make_int2(ss[j], __float_as_int(alp));
        }
    }
    // exit with g_cbar == 4*CSR_GRID; gather resets it to 0.
}

// ---------------------------------------------------------------------------
// Fused pull-gather + BN stats + grid barrier + normalize.
// One warp per dst node (grid-stride); lane owns 4 columns.
// Grid MUST be <= GATHER_GRID with __launch_bounds__(256,4): all blocks
// co-resident (4 x 148 SMs), so the software grid barrier cannot deadlock.
// ---------------------------------------------------------------------------
__device__ __forceinline__ void fh_acc(float4& acc, uint2 q, float a) {
    float2 fa = __half22float2(*(__half2*)&q.x);
    float2 fb = __half22float2(*(__half2*)&q.y);
    acc.x += fa.x * a;
    acc.y += fa.y * a;
    acc.z += fb.x * a;
    acc.w += fb.y * a;
}

__global__ void __launch_bounds__(256, 4)
gather_kernel(float4* __restrict__ agg, int n_nodes,
              const float* __restrict__ gamma,
              const float* __restrict__ beta,
              float inv_n) {
    const int lane   = threadIdx.x & 31;
    const int gwarp  = (blockIdx.x * blockDim.x + threadIdx.x) >> 5;
    const int nwarps = (gridDim.x * blockDim.x) >> 5;
    const uint2* fh = (const uint2*)g_fh;   // 32 uint2 per row

    // Reset the CSR kernel's barrier counter for the next launch/replay
    // (this kernel runs strictly after csr_kernel in stream order).
    if (blockIdx.x == 0 && threadIdx.x == 0) g_cbar = 0;

    float4 csum = make_float4(0.f, 0.f, 0.f, 0.f);
    float4 csq  = csum;

    for (int d = gwarp; d < n_nodes; d += nwarps) {
        int b = g_off[d], e = g_off[d + 1];
        float4 acc = make_float4(0.f, 0.f, 0.f, 0.f);
        int i = b;
        for (; i + 7 < e; i += 8) {
            int2 p[8];
            uint2 q[8];
#pragma unroll
            for (int j = 0; j < 8; j++) p[j] = __ldg(g_epack + i + j);
#pragma unroll
            for (int j = 0; j < 8; j++)
                q[j] = __ldg(fh + (size_t)p[j].x * 32 + lane);
#pragma unroll
            for (int j = 0; j < 8; j++)
                fh_acc(acc, q[j], __int_as_float(p[j].y));
        }
        if (i + 3 < e) {
            int2 p[4];
            uint2 q[4];
#pragma unroll
            for (int j = 0; j < 4; j++) p[j] = __ldg(g_epack + i + j);
#pragma unroll
            for (int j = 0; j < 4; j++)
                q[j] = __ldg(fh + (size_t)p[j].x * 32 + lane);
#pragma unroll
            for (int j = 0; j < 4; j++)
                fh_acc(acc, q[j], __int_as_float(p[j].y));
            i += 4;
        }
        for (; i < e; i++) {
            int2 p0 = __ldg(g_epack + i);
            uint2 q0 = __ldg(fh + (size_t)p0.x * 32 + lane);
            fh_acc(acc, q0, __int_as_float(p0.y));
        }
        agg[(size_t)d * 32 + lane] = acc;
        csum.x += acc.x; csum.y += acc.y; csum.z += acc.z; csum.w += acc.w;
        csq.x  += acc.x * acc.x; csq.y += acc.y * acc.y;
        csq.z  += acc.z * acc.z; csq.w += acc.w * acc.w;
    }

    // Block-level stats reduction: lane L of every warp owns columns 4L..4L+3.
    __shared__ float4 s_sum[256], s_sq[256];
    __shared__ float  s_scale[128], s_shift[128];
    s_sum[threadIdx.x] = csum;
    s_sq[threadIdx.x]  = csq;
    __syncthreads();
    if (threadIdx.x < 32) {
        float4 ts = make_float4(0.f, 0.f, 0.f, 0.f);
        float4 tq = ts;
        for (int w = 0; w < 8; w++) {
            float4 a = s_sum[w * 32 + threadIdx.x];
            float4 b = s_sq[w * 32 + threadIdx.x];
            ts.x += a.x; ts.y += a.y; ts.z += a.z; ts.w += a.w;
            tq.x += b.x; tq.y += b.y; tq.z += b.z; tq.w += b.w;
        }
        int c = threadIdx.x * 4;
        atomicAdd(&g_stats[c + 0], ts.x);
        atomicAdd(&g_stats[c + 1], ts.y);
        atomicAdd(&g_stats[c + 2], ts.z);
        atomicAdd(&g_stats[c + 3], ts.w);
        atomicAdd(&g_stats[128 + c + 0], tq.x);
        atomicAdd(&g_stats[128 + c + 1], tq.y);
        atomicAdd(&g_stats[128 + c + 2], tq.z);
        atomicAdd(&g_stats[128 + c + 3], tq.w);
    }
    __threadfence();
    __syncthreads();

    // Grid barrier (all blocks co-resident by launch_bounds + grid size).
    if (threadIdx.x == 0) {
        atomicAdd(&g_bar, 1);
        while (*(volatile int*)&g_bar < gridDim.x) { }
    }
    __syncthreads();
    __threadfence();

    // Per-block finalize: fold mean/var/gamma/beta into scale & shift.
    if (threadIdx.x < 128) {
        int c = threadIdx.x;
        float mean  = g_stats[c] * inv_n;
        float var   = g_stats[128 + c] * inv_n - mean * mean;
        float scale = rsqrtf(var + BN_EPS) * __ldg(gamma + c);
        s_scale[c] = scale;
        s_shift[c] = __ldg(beta + c) - mean * scale;
    }
    __syncthreads();

    // Normalize the same node set in place (agg rows are L2-hot).
    float4 sc = ((const float4*)s_scale)[lane];
    float4 sh = ((const float4*)s_shift)[lane];
    for (int d = gwarp; d < n_nodes; d += nwarps) {
        float4 v = agg[(size_t)d * 32 + lane];
        v.x = v.x * sc.x + sh.x;
        v.y = v.y * sc.y + sh.y;
        v.z = v.z * sc.z + sh.z;
        v.w = v.w * sc.w + sh.w;
        agg[(size_t)d * 32 + lane] = v;
    }
}

// ---------------------------------------------------------------------------
// Inputs: x, weight, alpha, gamma, beta, src, dst, edge_type
// ---------------------------------------------------------------------------
extern "C" void kernel_launch(void* const* d_in, const int* in_sizes, int n_in,
                              void* d_out, int out_size) {
    const float* x     = (const float*)d_in[0];
    const float* w     = (const float*)d_in[1];
    const float* alpha = (const float*)d_in[2];
    const float* gamma = (const float*)d_in[3];
    const float* beta  = (const float*)d_in[4];
    const int*   src   = (const int*)d_in[5];
    const int*   dst   = (const int*)d_in[6];
    const int*   et    = (const int*)d_in[7];
    float* out = (float*)d_out;

    int n_edges = in_sizes[5];
    int n_rows  = in_sizes[0] / D;            // 100000

    // Fork: CSR build on the origin stream (launched first so its 592 blocks
    // claim residency), GEMM on g_s2 — parallel branches under graph capture.
    cudaEventRecord(g_evFork, 0);
    cudaStreamWaitEvent(g_s2, g_evFork, 0);

    csr_kernel<<<CSR_GRID, 256>>>((const int4*)src, (const int4*)dst,
                                  (const int4*)et, alpha, n_rows, n_edges);

    gemm_kernel<<<dim3((n_rows + 127) / 128, 2), 256, 0, g_s2>>>(x, w, n_rows);
    cudaEventRecord(g_evJoin, g_s2);

    cudaStreamWaitEvent(0, g_evJoin, 0);  // join GEMM branch
    gather_kernel<<<GATHER_GRID, 256>>>((float4*)out, n_rows, gamma, beta,
                                        1.0f / (float)n_rows);
}

// round 15
// speedup vs baseline: 1.1476x; 1.1476x over previous
#include <cuda_runtime.h>
#include <cuda_bf16.h>
#include <cuda_fp16.h>

#define D 128
#define NREL_HALF 24
#define BN_EPS 1e-5f
#define MAX_NODES 100000
#define MAX_EDGES 1600000
#define SCAN_CHUNK 2048   // elements per scanA block (256 threads * 8)
#define GATHER_GRID 592   // 4 blocks/SM x 148 SMs: co-residency guaranteed

// Scratch: device globals (no allocations allowed).
__device__ __half g_fh[MAX_NODES * 128];     // 25.6 MB: x @ W in fp16
__device__ int    g_cnt[MAX_NODES];          // per-dst degree
__device__ int    g_off[MAX_NODES + 1];      // CSR offsets
__device__ int    g_cursor[MAX_NODES];       // reorder cursors
__device__ int2   g_epack[MAX_EDGES];        // CSR: {src, alpha_bits} per slot
__device__ int    g_bsums[64];               // scan block sums (49 used)
__device__ float  g_stats[256];              // col sums / col sumsq
__device__ int    g_bar;                     // gather grid-barrier counter

// Host-side stream/events for fork-join overlap (created once; host resources
// only — no device memory). Graph capture records these as parallel branches.
static cudaStream_t g_s2;
static cudaEvent_t  g_evFork, g_evScan, g_evJoin;
static struct _StreamInit {
    _StreamInit() {
        cudaStreamCreateWithFlags(&g_s2, cudaStreamNonBlocking);
        cudaEventCreateWithFlags(&g_evFork, cudaEventDisableTiming);
        cudaEventCreateWithFlags(&g_evScan, cudaEventDisableTiming);
        cudaEventCreateWithFlags(&g_evJoin, cudaEventDisableTiming);
    }
} g_streamInit;

// ---------------------------------------------------------------------------
// Zero degree counters (int4) + stats + gather barrier (tiny).
// ---------------------------------------------------------------------------
__global__ void zero_kernel(int n_nodes4) {
    int i = blockIdx.x * blockDim.x + threadIdx.x;
    if (i < n_nodes4) ((int4*)g_cnt)[i] = make_int4(0, 0, 0, 0);
    if (i < 256) g_stats[i] = 0.f;
    if (i == 0) g_bar = 0;
}

// ---------------------------------------------------------------------------
// feats = x @ W on tensor cores: 3-term bf16 split (hi*hi + hi*lo + lo*hi),
// fp32 accumulate, fp16 output.
//
// Grid: (rows/128, 2). Block = 256 threads = 8 warps; warp owns 16 rows.
// ---------------------------------------------------------------------------
__device__ __forceinline__ void cvt_split2(float2 v, unsigned& hi, unsigned& lo) {
    __nv_bfloat16 h0 = __float2bfloat16(v.x);
    __nv_bfloat16 h1 = __float2bfloat16(v.y);
    __nv_bfloat16 l0 = __float2bfloat16(v.x - __bfloat162float(h0));
    __nv_bfloat16 l1 = __float2bfloat16(v.y - __bfloat162float(h1));
    hi = (unsigned)__bfloat16_as_ushort(h0) |
         ((unsigned)__bfloat16_as_ushort(h1) << 16);
    lo = (unsigned)__bfloat16_as_ushort(l0) |
         ((unsigned)__bfloat16_as_ushort(l1) << 16);
}

#define MMA_BF16(d, a, b)                                                   \
    asm volatile(                                                           \
        "mma.sync.aligned.m16n8k16.row.col.f32.bf16.bf16.f32 "              \
        "{%0,%1,%2,%3}, {%4,%5,%6,%7}, {%8,%9}, {%0,%1,%2,%3};"             \
        : "+f"(d[0]), "+f"(d[1]), "+f"(d[2]), "+f"(d[3])                    \
        : "r"(a[0]), "r"(a[1]), "r"(a[2]), "r"(a[3]), "r"(b.x), "r"(b.y))

__global__ void gemm_kernel(const float* __restrict__ x,
                            const float* __restrict__ w,
                            int n_rows) {
    // [split][n-tile t][k-tile u][lane] -> uint2 {b0, b1}; 32 KB total.
    __shared__ uint2 sW[2][8][8][32];

    const int tid  = threadIdx.x;
    const int ch   = blockIdx.y;           // 64-col half
    const int lane = tid & 31;
    const int wid  = tid >> 5;

    // Stage + split W[k][ch*64+n] into fragment layout (8192 elements).
    for (int idx = tid; idx < 8192; idx += 256) {
        int k = idx >> 6, n = idx & 63;
        float v = __ldg(w + k * 128 + ch * 64 + n);
        __nv_bfloat16 h = __float2bfloat16(v);
        __nv_bfloat16 l = __float2bfloat16(v - __bfloat162float(h));
        int t = n >> 3, nin = n & 7;
        int u = k >> 4, kin = k & 15;
        int reg = (kin >> 3) & 1;          // b0 (k 0-7) or b1 (k 8-15)
        int half = kin & 1;
        int ln = nin * 4 + ((kin & 7) >> 1);
        unsigned short* ph = (unsigned short*)&sW[0][t][u][ln];
        unsigned short* pl = (unsigned short*)&sW[1][t][u][ln];
        ph[reg * 2 + half] = __bfloat16_as_ushort(h);
        pl[reg * 2 + half] = __bfloat16_as_ushort(l);
    }
    __syncthreads();

    const int r0   = blockIdx.x * 128 + wid * 16;
    const int rA   = r0 + (lane >> 2);          // rows lane/4 and +8
    const int rB   = rA + 8;
    const int rAc  = min(rA, n_rows - 1);       // clamped for loads
    const int rBc  = min(rB, n_rows - 1);
    const int kcol = (lane & 3) * 2;

    const float* xA = x + (size_t)rAc * 128;
    const float* xB = x + (size_t)rBc * 128;

    float acc[8][4];
#pragma unroll
    for (int t = 0; t < 8; t++)
#pragma unroll
        for (int j = 0; j < 4; j++) acc[t][j] = 0.f;

#pragma unroll
    for (int u = 0; u < 8; u++) {
        int k0 = u * 16 + kcol;
        float2 vA0 = *(const float2*)(xA + k0);
        float2 vA1 = *(const float2*)(xA + k0 + 8);
        float2 vB0 = *(const float2*)(xB + k0);
        float2 vB1 = *(const float2*)(xB + k0 + 8);
        unsigned ahi[4], alo[4];
        cvt_split2(vA0, ahi[0], alo[0]);
        cvt_split2(vB0, ahi[1], alo[1]);
        cvt_split2(vA1, ahi[2], alo[2]);
        cvt_split2(vB1, ahi[3], alo[3]);
#pragma unroll
        for (int t = 0; t < 8; t++) {
            uint2 bh = sW[0][t][u][lane];
            uint2 bl = sW[1][t][u][lane];
            MMA_BF16(acc[t], ahi, bh);
            MMA_BF16(acc[t], ahi, bl);
            MMA_BF16(acc[t], alo, bh);
        }
    }

    // Epilogue: fp16 half2 stores, guarded for the ragged last block.
    const int cbase = ch * 64 + kcol;  // (lane&3)*2 within each n-tile
    if (rA < n_rows) {
        __half* po = g_fh + (size_t)rA * 128 + cbase;
#pragma unroll
        for (int t = 0; t < 8; t++)
            *(__half2*)(po + t * 8) = __floats2half2_rn(acc[t][0], acc[t][1]);
    }
    if (rB < n_rows) {
        __half* po = g_fh + (size_t)rB * 128 + cbase;
#pragma unroll
        for (int t = 0; t < 8; t++)
            *(__half2*)(po + t * 8) = __floats2half2_rn(acc[t][2], acc[t][3]);
    }
}

// ---------------------------------------------------------------------------
// Histogram of destinations (int4 loads, 4 edges per thread).
// ---------------------------------------------------------------------------
__global__ void hist_kernel(const int4* __restrict__ dst4, int n_edges4) {
    int i = blockIdx.x * blockDim.x + threadIdx.x;
    if (i >= n_edges4) return;
    int4 d = __ldg(dst4 + i);
    atomicAdd(&g_cnt[d.x], 1);
    atomicAdd(&g_cnt[d.y], 1);
    atomicAdd(&g_cnt[d.z], 1);
    atomicAdd(&g_cnt[d.w], 1);
}

// ---------------------------------------------------------------------------
// Two-level exclusive scan of g_cnt -> g_off (+ block sums).
// ---------------------------------------------------------------------------
__global__ void scanA_kernel(int n) {
    __shared__ int wsum[8];
    int t = threadIdx.x;
    int base = blockIdx.x * SCAN_CHUNK + t * 8;
    int v[8];
    int run = 0;
#pragma unroll
    for (int j = 0; j < 8; j++) {
        int idx = base + j;
        int c = (idx < n) ? g_cnt[idx] : 0;
        v[j] = run;
        run += c;
    }
    int lane = t & 31, w = t >> 5;
    int inc = run;
#pragma unroll
    for (int o = 1; o < 32; o <<= 1) {
        int y = __shfl_up_sync(0xffffffffu, inc, o);
        if (lane >= o) inc += y;
    }
    if (lane == 31) wsum[w] = inc;
    __syncthreads();
    if (t == 0) {
        int s = 0;
#pragma unroll
        for (int i = 0; i < 8; i++) { int c = wsum[i]; wsum[i] = s; s += c; }
        g_bsums[blockIdx.x] = s;
    }
    __syncthreads();
    int excl = inc - run + wsum[w];
#pragma unroll
    for (int j = 0; j < 8; j++) {
        int idx = base + j;
        if (idx < n) g_off[idx] = excl + v[j];
    }
}

__global__ void scanB_kernel(int nb) {
    __shared__ int s[64];
    int t = threadIdx.x;
    if (t < nb) s[t] = g_bsums[t];
    __syncthreads();
    if (t == 0) {
        int r = 0;
        for (int i = 0; i < nb; i++) { int c = s[i]; s[i] = r; r += c; }
    }
    __syncthreads();
    if (t < nb) g_bsums[t] = s[t];
}

__global__ void scanC_kernel(int n, int n_edges) {
    int i = blockIdx.x * blockDim.x + threadIdx.x;
    if (i < n) {
        int o = g_off[i] + g_bsums[i / SCAN_CHUNK];
        g_off[i] = o;
        g_cursor[i] = o;
    }
    if (i == 0) g_off[n] = n_edges;
}

// ---------------------------------------------------------------------------
// Reorder edges into CSR slots; premultiply alpha. int4 index loads,
// single int2 store per edge. Range [begin4, end4) so two streams can split.
// ---------------------------------------------------------------------------
__global__ void reorder_kernel(const int4* __restrict__ src4,
                               const int4* __restrict__ dst4,
                               const int4* __restrict__ et4,
                               const float* __restrict__ alpha,
                               int begin4, int end4) {
    int i = begin4 + blockIdx.x * blockDim.x + threadIdx.x;
    if (i >= end4) return;
    int4 s = __ldg(src4 + i);
    int4 d = __ldg(dst4 + i);
    int4 t = __ldg(et4 + i);
    const int ss[4] = {s.x, s.y, s.z, s.w};
    const int dd[4] = {d.x, d.y, d.z, d.w};
    const int tt[4] = {t.x, t.y, t.z, t.w};
#pragma unroll
    for (int j = 0; j < 4; j++) {
        int ty = tt[j];
        int tr = (ty >= NREL_HALF) ? ty - NREL_HALF : ty + NREL_HALF;
        float alp = __ldg(alpha + ty) + __ldg(alpha + tr);
        int pos = atomicAdd(&g_cursor[dd[j]], 1);
        g_epack[pos] = make_int2(ss[j], __float_as_int(alp));
    }
}

// ---------------------------------------------------------------------------
// Fused pull-gather + BN stats + grid barrier + normalize.
// One warp per dst node (grid-stride); lane owns 4 columns.
// Grid MUST be <= GATHER_GRID with __launch_bounds__(256,4): all blocks
// co-resident (4 x 148 SMs), so the software grid barrier cannot deadlock.
// ---------------------------------------------------------------------------
__device__ __forceinline__ void fh_acc(float4& acc, uint2 q, float a) {
    float2 fa = __half22float2(*(__half2*)&q.x);
    float2 fb = __half22float2(*(__half2*)&q.y);
    acc.x += fa.x * a;
    acc.y += fa.y * a;
    acc.z += fb.x * a;
    acc.w += fb.y * a;
}

__global__ void __launch_bounds__(256, 4)
gather_kernel(float4* __restrict__ agg, int n_nodes,
              const float* __restrict__ gamma,
              const float* __restrict__ beta,
              float inv_n) {
    const int lane   = threadIdx.x & 31;
    const int gwarp  = (blockIdx.x * blockDim.x + threadIdx.x) >> 5;
    const int nwarps = (gridDim.x * blockDim.x) >> 5;
    const uint2* fh = (const uint2*)g_fh;   // 32 uint2 per row

    float4 csum = make_float4(0.f, 0.f, 0.f, 0.f);
    float4 csq  = csum;

    for (int d = gwarp; d < n_nodes; d += nwarps) {
        int b = g_off[d], e = g_off[d + 1];
        float4 acc = make_float4(0.f, 0.f, 0.f, 0.f);
        int i = b;
        for (; i + 7 < e; i += 8) {
            int2 p[8];
            uint2 q[8];
#pragma unroll
            for (int j = 0; j < 8; j++) p[j] = __ldg(g_epack + i + j);
#pragma unroll
            for (int j = 0; j < 8; j++)
                q[j] = __ldg(fh + (size_t)p[j].x * 32 + lane);
#pragma unroll
            for (int j = 0; j < 8; j++)
                fh_acc(acc, q[j], __int_as_float(p[j].y));
        }
        if (i + 3 < e) {
            int2 p[4];
            uint2 q[4];
#pragma unroll
            for (int j = 0; j < 4; j++) p[j] = __ldg(g_epack + i + j);
#pragma unroll
            for (int j = 0; j < 4; j++)
                q[j] = __ldg(fh + (size_t)p[j].x * 32 + lane);
#pragma unroll
            for (int j = 0; j < 4; j++)
                fh_acc(acc, q[j], __int_as_float(p[j].y));
            i += 4;
        }
        for (; i < e; i++) {
            int2 p0 = __ldg(g_epack + i);
            uint2 q0 = __ldg(fh + (size_t)p0.x * 32 + lane);
            fh_acc(acc, q0, __int_as_float(p0.y));
        }
        agg[(size_t)d * 32 + lane] = acc;
        csum.x += acc.x; csum.y += acc.y; csum.z += acc.z; csum.w += acc.w;
        csq.x  += acc.x * acc.x; csq.y += acc.y * acc.y;
        csq.z  += acc.z * acc.z; csq.w += acc.w * acc.w;
    }

    // Block-level stats reduction: lane L of every warp owns columns 4L..4L+3.
    __shared__ float4 s_sum[256], s_sq[256];
    __shared__ float  s_scale[128], s_shift[128];
    s_sum[threadIdx.x] = csum;
    s_sq[threadIdx.x]  = csq;
    __syncthreads();
    if (threadIdx.x < 32) {
        float4 ts = make_float4(0.f, 0.f, 0.f, 0.f);
        float4 tq = ts;
        for (int w = 0; w < 8; w++) {
            float4 a = s_sum[w * 32 + threadIdx.x];
            float4 b = s_sq[w * 32 + threadIdx.x];
            ts.x += a.x; ts.y += a.y; ts.z += a.z; ts.w += a.w;
            tq.x += b.x; tq.y += b.y; tq.z += b.z; tq.w += b.w;
        }
        int c = threadIdx.x * 4;
        atomicAdd(&g_stats[c + 0], ts.x);
        atomicAdd(&g_stats[c + 1], ts.y);
        atomicAdd(&g_stats[c + 2], ts.z);
        atomicAdd(&g_stats[c + 3], ts.w);
        atomicAdd(&g_stats[128 + c + 0], tq.x);
        atomicAdd(&g_stats[128 + c + 1], tq.y);
        atomicAdd(&g_stats[128 + c + 2], tq.z);
        atomicAdd(&g_stats[128 + c + 3], tq.w);
    }
    __threadfence();
    __syncthreads();

    // Grid barrier (all blocks co-resident by launch_bounds + grid size).
    if (threadIdx.x == 0) {
        atomicAdd(&g_bar, 1);
        while (*(volatile int*)&g_bar < gridDim.x) { }
    }
    __syncthreads();
    __threadfence();

    // Per-block finalize: fold mean/var/gamma/beta into scale & shift.
    if (threadIdx.x < 128) {
        int c = threadIdx.x;
        float mean  = g_stats[c] * inv_n;
        float var   = g_stats[128 + c] * inv_n - mean * mean;
        float scale = rsqrtf(var + BN_EPS) * __ldg(gamma + c);
        s_scale[c] = scale;
        s_shift[c] = __ldg(beta + c) - mean * scale;
    }
    __syncthreads();

    // Normalize the same node set in place (agg rows are L2-hot).
    float4 sc = ((const float4*)s_scale)[lane];
    float4 sh = ((const float4*)s_shift)[lane];
    for (int d = gwarp; d < n_nodes; d += nwarps) {
        float4 v = agg[(size_t)d * 32 + lane];
        v.x = v.x * sc.x + sh.x;
        v.y = v.y * sc.y + sh.y;
        v.z = v.z * sc.z + sh.z;
        v.w = v.w * sc.w + sh.w;
        agg[(size_t)d * 32 + lane] = v;
    }
}

// ---------------------------------------------------------------------------
// Inputs: x, weight, alpha, gamma, beta, src, dst, edge_type
// ---------------------------------------------------------------------------
extern "C" void kernel_launch(void* const* d_in, const int* in_sizes, int n_in,
                              void* d_out, int out_size) {
    const float* x     = (const float*)d_in[0];
    const float* w     = (const float*)d_in[1];
    const float* alpha = (const float*)d_in[2];
    const float* gamma = (const float*)d_in[3];
    const float* beta  = (const float*)d_in[4];
    const int*   src   = (const int*)d_in[5];
    const int*   dst   = (const int*)d_in[6];
    const int*   et    = (const int*)d_in[7];
    float* out = (float*)d_out;

    int n_edges  = in_sizes[5];
    int n_rows   = in_sizes[0] / D;                        // 100000
    int n_rows4  = n_rows / 4;                             // divisible
    int nscan    = (n_rows + SCAN_CHUNK - 1) / SCAN_CHUNK; // 49
    int n_edges4 = n_edges / 4;                            // 400000
    int half4    = n_edges4 / 2;                           // 200000

    // Fork GEMM immediately (no dependency on zero/CSR chain).
    cudaEventRecord(g_evFork, 0);
    cudaStreamWaitEvent(g_s2, g_evFork, 0);
    gemm_kernel<<<dim3((n_rows + 127) / 128, 2), 256, 0, g_s2>>>(x, w, n_rows);

    // CSR chain on the origin stream.
    zero_kernel<<<(n_rows4 + 255) / 256, 256>>>(n_rows4);
    hist_kernel<<<(n_edges4 + 255) / 256, 256>>>((const int4*)dst, n_edges4);
    scanA_kernel<<<nscan, 256>>>(n_rows);
    scanB_kernel<<<1, 64>>>(nscan);
    scanC_kernel<<<(n_rows + 255) / 256, 256>>>(n_rows, n_edges);

    // Split reorder: second half on g_s2 (after GEMM + scanC), first half here.
    cudaEventRecord(g_evScan, 0);
    cudaStreamWaitEvent(g_s2, g_evScan, 0);
    reorder_kernel<<<(half4 + 255) / 256, 256, 0, g_s2>>>(
        (const int4*)src, (const int4*)dst, (const int4*)et, alpha,
        half4, n_edges4);
    cudaEventRecord(g_evJoin, g_s2);

    reorder_kernel<<<(half4 + 255) / 256, 256>>>(
        (const int4*)src, (const int4*)dst, (const int4*)et, alpha,
        0, half4);

    cudaStreamWaitEvent(0, g_evJoin, 0);  // join GEMM+reorder branch
    gather_kernel<<<GATHER_GRID, 256>>>((float4*)out, n_rows, gamma, beta,
                                        1.0f / (float)n_rows);
}